// round 1
// baseline (speedup 1.0000x reference)
#include <cuda_runtime.h>
#include <math.h>

// Problem constants
#define TZc 512
#define Bc  64
#define Hc  512
#define Ec  256
#define Vc  3000
#define Dc  5
#define VTc 3512          // V + TZ
#define GINc 1285         // E + 2H + D
#define XPADc 1288
#define G3c 1536          // 3H
#define LTc 6512          // V + VT

// ---------------- scratch (device globals; no allocation allowed) ------------
// g_accbuf layout: [0]=e_z, [1]=e_u, [2]=ctx_z, [3]=ctx_u, [4]=cs  (each 64x512)
__device__ float g_accbuf[5 * 32768];
__device__ float g_hw[2 * 32768];      // hWz, hWu  (h0 @ W[:H] + b)
__device__ float g_x[Bc * XPADc];      // GRU input (padded stride)
__device__ float g_gi[Bc * G3c];
__device__ float g_gh[Bc * G3c];
__device__ float g_h1[Bc * Hc];
__device__ float g_ecs[Bc * TZc];
__device__ float g_mrow[Bc];
__device__ float g_logits[Bc * LTc];

// ---------------- f32x2 packed-FMA helpers (sm_103a) -------------------------
__device__ __forceinline__ unsigned long long dup2(float x) {
    unsigned long long r;
    unsigned xi = __float_as_uint(x);
    asm("mov.b64 %0, {%1, %1};" : "=l"(r) : "r"(xi));
    return r;
}
__device__ __forceinline__ void fma2(unsigned long long &acc,
                                     unsigned long long a, unsigned long long b) {
    asm("fma.rn.f32x2 %0, %1, %2, %0;" : "+l"(acc) : "l"(a), "l"(b));
}
__device__ __forceinline__ float2 unpk(unsigned long long a) {
    unsigned lo, hi;
    asm("mov.b64 {%0, %1}, %2;" : "=r"(lo), "=r"(hi) : "l"(a));
    float2 c; c.x = __uint_as_float(lo); c.y = __uint_as_float(hi);
    return c;
}

// ---------------- block reductions -------------------------------------------
__device__ __forceinline__ float blockReduceMax(float v, float* sh) {
    #pragma unroll
    for (int o = 16; o; o >>= 1) v = fmaxf(v, __shfl_xor_sync(0xffffffffu, v, o));
    if ((threadIdx.x & 31) == 0) sh[threadIdx.x >> 5] = v;
    __syncthreads();
    float r = sh[0];
    int nw = (blockDim.x + 31) >> 5;
    for (int j = 1; j < nw; j++) r = fmaxf(r, sh[j]);
    __syncthreads();
    return r;
}
__device__ __forceinline__ float blockReduceSum(float v, float* sh) {
    #pragma unroll
    for (int o = 16; o; o >>= 1) v += __shfl_xor_sync(0xffffffffu, v, o);
    if ((threadIdx.x & 31) == 0) sh[threadIdx.x >> 5] = v;
    __syncthreads();
    float r = 0.f;
    int nw = (blockDim.x + 31) >> 5;
    for (int j = 0; j < nw; j++) r += sh[j];
    __syncthreads();
    return r;
}

// ---------------- kernels -----------------------------------------------------

__global__ void k_zero() {
    int i = blockIdx.x * blockDim.x + threadIdx.x;
    if (i < 5 * 32768) g_accbuf[i] = 0.f;
}

// hW[b,k] = sum_j h0[b,j] * W[j,k] + bias[k]   (W = first H rows of Wz/Wu)
__global__ void k_hW(const float* __restrict__ h0,
                     const float* __restrict__ Wz, const float* __restrict__ bz,
                     const float* __restrict__ Wu, const float* __restrict__ bu) {
    int b = blockIdx.x, which = blockIdx.y, k = threadIdx.x;
    const float* W  = which ? Wu : Wz;
    const float* bb = which ? bu : bz;
    float* o = g_hw + which * 32768;
    __shared__ float sh[512];
    sh[k] = h0[b * 512 + k];
    __syncthreads();
    float acc = bb[k];
    #pragma unroll 8
    for (int j = 0; j < 512; j++) acc += sh[j] * W[j * 512 + k];
    o[b * 512 + k] = acc;
}

// Fused GEMM + tanh + dot epilogue.
// MODE 0: attn-z : bias = g_hw[0] (per-b), v = ext_v (vz),  out = e_z
// MODE 1: attn-u : bias = g_hw[1] (per-b), v = ext_v (vu),  out = e_u
// MODE 2: cs     : bias = ext_bias (bc2),  v = g_h1 (per-b), out = cs
// out[b*512 + t] += sum_k tanh(A[m,:]·W2[:,k] + bias) * v ,  m = t*64 + b
template<int MODE>
__global__ void __launch_bounds__(256)
k_fused_gemm(const float* __restrict__ A, const float* __restrict__ W2,
             const float* __restrict__ ext_bias, const float* __restrict__ ext_v) {
    __shared__ float As[16][65];
    __shared__ float Bs[16][68];
    __shared__ float rs[64][17];

    const int m0 = blockIdx.y * 64;
    const int n0 = blockIdx.x * 64;
    const int tid = threadIdx.x;
    const int tx = tid & 15;
    const int ty = tid >> 4;

    unsigned long long acc[4][2] = {};

    const int lrow = tid >> 2;
    const int lq   = (tid & 3) << 2;
    const int bkr  = tid >> 4;
    const int bnq  = (tid & 15) << 2;

    for (int kk = 0; kk < 512; kk += 16) {
        float4 a4 = *(const float4*)(A + (size_t)(m0 + lrow) * 512 + kk + lq);
        As[lq + 0][lrow] = a4.x; As[lq + 1][lrow] = a4.y;
        As[lq + 2][lrow] = a4.z; As[lq + 3][lrow] = a4.w;
        float4 b4 = *(const float4*)(W2 + (size_t)(kk + bkr) * 512 + n0 + bnq);
        *(float4*)&Bs[bkr][bnq] = b4;
        __syncthreads();
        #pragma unroll
        for (int k = 0; k < 16; k++) {
            unsigned long long b0 = *(const unsigned long long*)&Bs[k][tx * 4];
            unsigned long long b1 = *(const unsigned long long*)&Bs[k][tx * 4 + 2];
            #pragma unroll
            for (int i = 0; i < 4; i++) {
                unsigned long long ai = dup2(As[k][ty * 4 + i]);
                fma2(acc[i][0], ai, b0);
                fma2(acc[i][1], ai, b1);
            }
        }
        __syncthreads();
    }

    float* outp = g_accbuf + (MODE == 2 ? 4 : MODE) * 32768;

    #pragma unroll
    for (int i = 0; i < 4; i++) {
        int mr = m0 + ty * 4 + i;
        int b = mr & 63;
        const float* bp = (MODE < 2) ? (g_hw + MODE * 32768 + b * 512) : ext_bias;
        const float* vp = (MODE < 2) ? ext_v : (g_h1 + b * 512);
        float s = 0.f;
        #pragma unroll
        for (int p = 0; p < 2; p++) {
            float2 c = unpk(acc[i][p]);
            int k0 = n0 + tx * 4 + 2 * p;
            s += tanhf(c.x + bp[k0])     * vp[k0];
            s += tanhf(c.y + bp[k0 + 1]) * vp[k0 + 1];
        }
        rs[ty * 4 + i][tx] = s;
    }
    __syncthreads();
    if (tid < 64) {
        float s = 0.f;
        #pragma unroll
        for (int j = 0; j < 16; j++) s += rs[tid][j];
        int mr = m0 + tid;
        int b = mr & 63, t = mr >> 6;
        atomicAdd(&outp[b * 512 + t], s);
    }
}

// softmax over t per (which,b); rows 0..63 = e_z, 64..127 = e_u (contiguous)
__global__ void k_softmax_rows() {
    __shared__ float sh[16];
    float* row = g_accbuf + (size_t)blockIdx.x * 512;
    float x = row[threadIdx.x];
    float m = blockReduceMax(x, sh);
    float e = expf(x - m);
    float s = blockReduceSum(e, sh);
    row[threadIdx.x] = e / s;
}

// ctx[b,h] += sum_{t in slice} a[b,t] * enc[t,b,h]
__global__ void k_ctx(const float* __restrict__ z_enc, const float* __restrict__ u_enc) {
    int which = blockIdx.z;
    int b  = blockIdx.y;
    int t0 = blockIdx.x * 64;
    int h  = threadIdx.x;
    const float* enc = which ? u_enc : z_enc;
    const float* a   = g_accbuf + which * 32768 + b * 512;
    float* ctx = g_accbuf + (2 + which) * 32768 + b * 512;
    __shared__ float sa[64];
    if (h < 64) sa[h] = a[t0 + h];
    __syncthreads();
    float s = 0.f;
    #pragma unroll 8
    for (int tt = 0; tt < 64; tt++)
        s += sa[tt] * enc[((size_t)(t0 + tt) * 64 + b) * 512 + h];
    atomicAdd(&ctx[h], s);
}

// x = [m_embed(256), u_ctx(512), z_ctx(512), degree(5)]
__global__ void k_assemble(const float* __restrict__ emb, const int* __restrict__ mt,
                           const float* __restrict__ degree) {
    int b = blockIdx.x, tid = threadIdx.x;
    float* xr = g_x + b * XPADc;
    const float* ctxz = g_accbuf + 2 * 32768 + b * 512;
    const float* ctxu = g_accbuf + 3 * 32768 + b * 512;
    int m = mt[b];
    if (tid < 256) xr[tid] = emb[(size_t)m * Ec + tid];
    xr[256 + tid] = ctxu[tid];
    xr[768 + tid] = ctxz[tid];
    if (tid < 5) xr[1280 + tid] = degree[b * Dc + tid];
}

// gi[b,g] = b_ih[g] + x[b,:]·W_ih[g,:] ; gh[b,g] = b_hh[g] + h0[b,:]·W_hh[g,:]
__global__ void __launch_bounds__(256)
k_gates(const float* __restrict__ W_ih, const float* __restrict__ W_hh,
        const float* __restrict__ b_ih, const float* __restrict__ b_hh,
        const float* __restrict__ h0) {
    int b = threadIdx.x & 63;
    int g = blockIdx.x * 4 + (threadIdx.x >> 6);
    const float* xr = g_x + b * XPADc;
    const float* wr = W_ih + (size_t)g * GINc;
    float acc = b_ih[g];
    #pragma unroll 5
    for (int j = 0; j < GINc; j++) acc += xr[j] * wr[j];
    g_gi[b * G3c + g] = acc;
    const float* hr = h0 + b * 512;
    const float* wh = W_hh + (size_t)g * 512;
    float a2 = b_hh[g];
    #pragma unroll 8
    for (int j = 0; j < 512; j++) a2 += hr[j] * wh[j];
    g_gh[b * G3c + g] = a2;
}

__global__ void k_h1(const float* __restrict__ h0, float* __restrict__ out) {
    int b = blockIdx.x, h = threadIdx.x;
    float ir = g_gi[b * G3c + h],        hr = g_gh[b * G3c + h];
    float iz = g_gi[b * G3c + 512 + h],  hz = g_gh[b * G3c + 512 + h];
    float in_ = g_gi[b * G3c + 1024 + h], hn = g_gh[b * G3c + 1024 + h];
    float r = 1.f / (1.f + expf(-(ir + hr)));
    float z = 1.f / (1.f + expf(-(iz + hz)));
    float n = tanhf(in_ + r * hn);
    float hv = (1.f - z) * n + z * h0[b * 512 + h];
    g_h1[b * 512 + h] = hv;
    out[Bc * VTc + b * 512 + h] = hv;                 // h1 copy 1
    out[Bc * VTc + Bc * 512 + b * 512 + h] = hv;      // h1 copy 2
}

// gen_score[b,v] = [z_ctx,u_ctx,h1]·W_proj[:,v] + b_proj[v] -> logits[:, :3000]
__global__ void __launch_bounds__(128)
k_proj(const float* __restrict__ W_proj, const float* __restrict__ b_proj) {
    __shared__ float sx[8][G3c];
    int b0 = blockIdx.y * 8;
    int tid = threadIdx.x;
    for (int i = tid; i < 8 * G3c; i += 128) {
        int bl = i / G3c, j = i % G3c;
        int b = b0 + bl;
        float v;
        if (j < 512)       v = g_accbuf[2 * 32768 + b * 512 + j];          // z_ctx
        else if (j < 1024) v = g_accbuf[3 * 32768 + b * 512 + (j - 512)];  // u_ctx
        else               v = g_h1[b * 512 + (j - 1024)];
        sx[bl][j] = v;
    }
    __syncthreads();
    int v = blockIdx.x * 128 + tid;
    if (v >= Vc) return;
    float acc[8];
    float bp = b_proj[v];
    #pragma unroll
    for (int bl = 0; bl < 8; bl++) acc[bl] = bp;
    for (int j = 0; j < G3c; j++) {
        float w = W_proj[(size_t)j * Vc + v];
        #pragma unroll
        for (int bl = 0; bl < 8; bl++) acc[bl] += sx[bl][j] * w;
    }
    #pragma unroll
    for (int bl = 0; bl < 8; bl++)
        g_logits[(size_t)(b0 + bl) * LTc + v] = acc[bl];
}

// m[b] = max_t cs ; ecs = exp(cs - m)
__global__ void k_rowmax() {
    __shared__ float sh[16];
    int b = blockIdx.x, t = threadIdx.x;
    float c = g_accbuf[4 * 32768 + b * 512 + t];
    float m = blockReduceMax(c, sh);
    g_ecs[b * 512 + t] = expf(c - m);
    if (t == 0) g_mrow[b] = m;
}

// z_copy[b,v] = log(sum_t ecs[b,t]*sparse[b,t,v]) + m[b] -> logits[:, 3000:]
__global__ void __launch_bounds__(128)
k_zcopy(const float* __restrict__ sparse) {
    __shared__ float se[512];
    int b = blockIdx.y;
    int tid = threadIdx.x;
    for (int i = tid; i < 512; i += 128) se[i] = g_ecs[b * 512 + i];
    __syncthreads();
    int v = blockIdx.x * 128 + tid;
    if (v >= VTc) return;
    const float* sp = sparse + (size_t)b * TZc * VTc + v;
    float s = 0.f;
    #pragma unroll 4
    for (int t = 0; t < 512; t++) s += se[t] * sp[(size_t)t * VTc];
    g_logits[(size_t)b * LTc + Vc + v] = logf(s) + g_mrow[b];
}

// final softmax over 6512 + recombine: proba[v<3000]=gen+cpy[v]; tail = cpy[3000:]
__global__ void k_final(float* __restrict__ out) {
    __shared__ float sh[16];
    int b = blockIdx.x, tid = threadIdx.x;
    const float* l = g_logits + (size_t)b * LTc;
    float m = -1e30f;
    for (int i = tid; i < LTc; i += 512) m = fmaxf(m, l[i]);
    m = blockReduceMax(m, sh);
    float s = 0.f;
    for (int i = tid; i < LTc; i += 512) s += expf(l[i] - m);
    s = blockReduceSum(s, sh);
    float inv = 1.f / s;
    float* op = out + (size_t)b * VTc;
    for (int v = tid; v < Vc; v += 512)
        op[v] = (expf(l[v] - m) + expf(l[Vc + v] - m)) * inv;
    for (int k2 = tid; k2 < 512; k2 += 512)
        op[Vc + k2] = expf(l[2 * Vc + k2] - m) * inv;
}

// ---------------- launch ------------------------------------------------------
extern "C" void kernel_launch(void* const* d_in, const int* in_sizes, int n_in,
                              void* d_out, int out_size) {
    (void)in_sizes; (void)n_in; (void)out_size;
    const float* z_enc  = (const float*)d_in[0];
    const float* u_enc  = (const float*)d_in[1];
    const int*   mt     = (const int*)  d_in[2];
    const float* degree = (const float*)d_in[3];
    const float* h0     = (const float*)d_in[4];
    const float* sparse = (const float*)d_in[5];
    const float* emb    = (const float*)d_in[6];
    const float* Wz     = (const float*)d_in[7];
    const float* bz     = (const float*)d_in[8];
    const float* vz     = (const float*)d_in[9];
    const float* Wu     = (const float*)d_in[10];
    const float* bu     = (const float*)d_in[11];
    const float* vu     = (const float*)d_in[12];
    const float* W_ih   = (const float*)d_in[13];
    const float* W_hh   = (const float*)d_in[14];
    const float* b_ih   = (const float*)d_in[15];
    const float* b_hh   = (const float*)d_in[16];
    const float* W_proj = (const float*)d_in[17];
    const float* b_proj = (const float*)d_in[18];
    const float* Wc2    = (const float*)d_in[19];
    const float* bc2    = (const float*)d_in[20];
    float* out = (float*)d_out;

    k_zero<<<320, 512>>>();
    k_hW<<<dim3(Bc, 2), 512>>>(h0, Wz, bz, Wu, bu);

    // energy GEMMs: enc @ W[H:2H] fused tanh-dot  (M=32768, N=512, K=512)
    k_fused_gemm<0><<<dim3(8, 512), 256>>>(z_enc, Wz + Hc * Hc, nullptr, vz);
    k_fused_gemm<1><<<dim3(8, 512), 256>>>(u_enc, Wu + Hc * Hc, nullptr, vu);

    k_softmax_rows<<<128, 512>>>();
    k_ctx<<<dim3(8, Bc, 2), 512>>>(z_enc, u_enc);

    k_assemble<<<Bc, 512>>>(emb, mt, degree);
    k_gates<<<G3c / 4, 256>>>(W_ih, W_hh, b_ih, b_hh, h0);
    k_h1<<<Bc, 512>>>(h0, out);

    k_proj<<<dim3(24, 8), 128>>>(W_proj, b_proj);

    // cs GEMM: tanh(z_enc @ Wc2 + bc2) · h1
    k_fused_gemm<2><<<dim3(8, 512), 256>>>(z_enc, Wc2, bc2, g_h1);

    k_rowmax<<<Bc, 512>>>();
    k_zcopy<<<dim3(28, Bc), 128>>>(sparse);
    k_final<<<Bc, 512>>>(out);
}

// round 3
// speedup vs baseline: 1.5959x; 1.5959x over previous
#include <cuda_runtime.h>
#include <cuda_bf16.h>
#include <math.h>
#include <cstdint>

// Problem constants
#define TZc 512
#define Bc  64
#define Hc  512
#define Ec  256
#define Vc  3000
#define Dc  5
#define VTc 3512          // V + TZ
#define GINc 1285         // E + 2H + D
#define XPADc 1288
#define G3c 1536          // 3H
#define LTc 6512          // V + VT

// ---------------- scratch (device globals; no allocation allowed) ------------
// g_accbuf layout: [0]=e_z, [1]=e_u, [2]=ctx_z, [3]=ctx_u, [4]=cs  (each 64x512)
__device__ float g_accbuf[5 * 32768];
__device__ float g_hw[2 * 32768];      // hWz, hWu  (h0 @ W[:H] + b)
__device__ float g_x[Bc * XPADc];      // GRU input (padded stride)
__device__ float g_gi[Bc * G3c];
__device__ float g_gh[Bc * G3c];
__device__ float g_h1[Bc * Hc];
__device__ float g_ecs[Bc * TZc];
__device__ float g_mrow[Bc];
__device__ float g_logits[Bc * LTc];
// transposed split-bf16 weights: [gemm][n][k], gemm: 0=Wz2, 1=Wu2, 2=Wc2
__device__ __nv_bfloat16 g_wt_hi[3 * 512 * 512];
__device__ __nv_bfloat16 g_wt_lo[3 * 512 * 512];

// ---------------- helpers ------------------------------------------------------
__device__ __forceinline__ float tanh_fast(float x) {
    float y;
    asm("tanh.approx.f32 %0, %1;" : "=f"(y) : "f"(x));
    return y;
}
__device__ __forceinline__ void mma16816(float* c, const uint32_t* a, const uint32_t* b) {
    asm volatile(
        "mma.sync.aligned.m16n8k16.row.col.f32.bf16.bf16.f32 "
        "{%0,%1,%2,%3}, {%4,%5,%6,%7}, {%8,%9}, {%0,%1,%2,%3};"
        : "+f"(c[0]), "+f"(c[1]), "+f"(c[2]), "+f"(c[3])
        : "r"(a[0]), "r"(a[1]), "r"(a[2]), "r"(a[3]), "r"(b[0]), "r"(b[1]));
}

// ---------------- block reductions -------------------------------------------
__device__ __forceinline__ float blockReduceMax(float v, float* sh) {
    #pragma unroll
    for (int o = 16; o; o >>= 1) v = fmaxf(v, __shfl_xor_sync(0xffffffffu, v, o));
    if ((threadIdx.x & 31) == 0) sh[threadIdx.x >> 5] = v;
    __syncthreads();
    float r = sh[0];
    int nw = (blockDim.x + 31) >> 5;
    for (int j = 1; j < nw; j++) r = fmaxf(r, sh[j]);
    __syncthreads();
    return r;
}
__device__ __forceinline__ float blockReduceSum(float v, float* sh) {
    #pragma unroll
    for (int o = 16; o; o >>= 1) v += __shfl_xor_sync(0xffffffffu, v, o);
    if ((threadIdx.x & 31) == 0) sh[threadIdx.x >> 5] = v;
    __syncthreads();
    float r = 0.f;
    int nw = (blockDim.x + 31) >> 5;
    for (int j = 0; j < nw; j++) r += sh[j];
    __syncthreads();
    return r;
}

// ---------------- kernels -----------------------------------------------------

__global__ void k_zero() {
    int i = blockIdx.x * blockDim.x + threadIdx.x;
    if (i < 5 * 32768) g_accbuf[i] = 0.f;
}

// Transpose + split fp32 weights -> bf16 hi/lo [n][k].
// which 0: Wz[H:2H], 1: Wu[H:2H], 2: Wc2
__global__ void k_prep_w(const float* __restrict__ Wz, const float* __restrict__ Wu,
                         const float* __restrict__ Wc2) {
    __shared__ float ts[32][33];
    int which = blockIdx.z;
    const float* W = (which == 0) ? (Wz + 512 * 512) : (which == 1) ? (Wu + 512 * 512) : Wc2;
    int k0 = blockIdx.y * 32, n0 = blockIdx.x * 32;
    int tx = threadIdx.x, ty = threadIdx.y;   // 32 x 8
    #pragma unroll
    for (int j = 0; j < 32; j += 8)
        ts[ty + j][tx] = W[(size_t)(k0 + ty + j) * 512 + n0 + tx];
    __syncthreads();
    __nv_bfloat16* oh = g_wt_hi + (size_t)which * 262144;
    __nv_bfloat16* ol = g_wt_lo + (size_t)which * 262144;
    #pragma unroll
    for (int j = 0; j < 32; j += 8) {
        float x = ts[tx][ty + j];
        __nv_bfloat16 h = __float2bfloat16(x);
        __nv_bfloat16 l = __float2bfloat16(x - __bfloat162float(h));
        size_t idx = (size_t)(n0 + ty + j) * 512 + k0 + tx;
        oh[idx] = h; ol[idx] = l;
    }
}

// hW[b,k] = sum_j h0[b,j] * W[j,k] + bias[k]   (W = first H rows of Wz/Wu)
__global__ void k_hW(const float* __restrict__ h0,
                     const float* __restrict__ Wz, const float* __restrict__ bz,
                     const float* __restrict__ Wu, const float* __restrict__ bu) {
    int b = blockIdx.x, which = blockIdx.y, k = threadIdx.x;
    const float* W  = which ? Wu : Wz;
    const float* bb = which ? bu : bz;
    float* o = g_hw + which * 32768;
    __shared__ float sh[512];
    sh[k] = h0[b * 512 + k];
    __syncthreads();
    float acc = bb[k];
    #pragma unroll 8
    for (int j = 0; j < 512; j++) acc += sh[j] * W[j * 512 + k];
    o[b * 512 + k] = acc;
}

// ---------------- mma.sync fused GEMM + tanh-dot epilogue ---------------------
// gemm id (gemm_base + blockIdx.z): 0 = attn-z, 1 = attn-u, 2 = cs
// C = A(32768x512) @ W2(512x512); CTA tile 128(M) x 128(N), K chunk 64.
// out[b*512+t] += sum_n tanh(C[m,n] + bias) * v,  m = t*64+b
#define SA_STRIDE 72                      // bf16 elems per smem row (64 + 8 pad)
#define SM_TILE   (128 * SA_STRIDE)       // 9216 elems
#define GEMM_SMEM (4 * SM_TILE * 2 + 128 * 5 * 4)   // 73728 + 2560 = 76288 B
__global__ void __launch_bounds__(256, 1)
k_mma_gemm(const float* __restrict__ z_enc, const float* __restrict__ u_enc,
           const float* __restrict__ vz, const float* __restrict__ vu,
           const float* __restrict__ bc2, int gemm_base) {
    extern __shared__ char smem_raw[];
    __nv_bfloat16* sAh = (__nv_bfloat16*)smem_raw;
    __nv_bfloat16* sAl = sAh + SM_TILE;
    __nv_bfloat16* sBh = sAl + SM_TILE;
    __nv_bfloat16* sBl = sBh + SM_TILE;
    float* rs = (float*)(smem_raw + 4 * SM_TILE * 2);   // [128][5]

    const int tid = threadIdx.x;
    const int wid = tid >> 5;
    const int lane = tid & 31;
    const int gro = lane >> 2;     // groupID
    const int tig = lane & 3;      // thread-in-group
    const int wm = wid >> 2;       // 0..1  (M)
    const int wn = wid & 3;        // 0..3  (N)

    const int gid = gemm_base + blockIdx.z;
    const int m0 = blockIdx.x * 128;
    const int n0 = blockIdx.y * 128;

    const float* A = (gid == 1) ? u_enc : z_enc;
    const __nv_bfloat16* WtH = g_wt_hi + (size_t)gid * 262144;
    const __nv_bfloat16* WtL = g_wt_lo + (size_t)gid * 262144;

    float c[4][4][4];
    #pragma unroll
    for (int i = 0; i < 4; i++)
        #pragma unroll
        for (int j = 0; j < 4; j++)
            #pragma unroll
            for (int r = 0; r < 4; r++) c[i][j][r] = 0.f;

    for (int kk = 0; kk < 512; kk += 64) {
        // ---- load A chunk (128 x 64 fp32), split into bf16 hi/lo ----
        #pragma unroll
        for (int i = 0; i < 8; i++) {
            int idx = tid + i * 256;          // 0..2047 float4s
            int row = idx >> 4;
            int k4  = idx & 15;
            float4 v = ((const float4*)(A + (size_t)(m0 + row) * 512 + kk))[k4];
            float xs[4] = {v.x, v.y, v.z, v.w};
            union { uint2 u; __nv_bfloat16 h[4]; } ph, pl;
            #pragma unroll
            for (int j = 0; j < 4; j++) {
                __nv_bfloat16 hh = __float2bfloat16(xs[j]);
                ph.h[j] = hh;
                pl.h[j] = __float2bfloat16(xs[j] - __bfloat162float(hh));
            }
            int e = row * SA_STRIDE + k4 * 4;
            *(uint2*)(sAh + e) = ph.u;
            *(uint2*)(sAl + e) = pl.u;
        }
        // ---- load B chunk (128 n-rows x 64 k bf16, hi+lo) ----
        #pragma unroll
        for (int i = 0; i < 4; i++) {
            int idx = tid + i * 256;          // 0..1023 uint4s
            int row = idx >> 3;
            int kq  = idx & 7;
            int e = row * SA_STRIDE + kq * 8;
            *(uint4*)(sBh + e) = *(const uint4*)(WtH + (size_t)(n0 + row) * 512 + kk + kq * 8);
            *(uint4*)(sBl + e) = *(const uint4*)(WtL + (size_t)(n0 + row) * 512 + kk + kq * 8);
        }
        __syncthreads();

        #pragma unroll
        for (int ks = 0; ks < 4; ks++) {
            uint32_t ah[4][4], al[4][4], bh[4][2], bl[4][2];
            #pragma unroll
            for (int mt = 0; mt < 4; mt++) {
                int e0 = (wm * 64 + mt * 16 + gro) * SA_STRIDE + ks * 16 + tig * 2;
                ah[mt][0] = *(const uint32_t*)(sAh + e0);
                ah[mt][1] = *(const uint32_t*)(sAh + e0 + 8 * SA_STRIDE);
                ah[mt][2] = *(const uint32_t*)(sAh + e0 + 8);
                ah[mt][3] = *(const uint32_t*)(sAh + e0 + 8 * SA_STRIDE + 8);
                al[mt][0] = *(const uint32_t*)(sAl + e0);
                al[mt][1] = *(const uint32_t*)(sAl + e0 + 8 * SA_STRIDE);
                al[mt][2] = *(const uint32_t*)(sAl + e0 + 8);
                al[mt][3] = *(const uint32_t*)(sAl + e0 + 8 * SA_STRIDE + 8);
            }
            #pragma unroll
            for (int nt = 0; nt < 4; nt++) {
                int e0 = (wn * 32 + nt * 8 + gro) * SA_STRIDE + ks * 16 + tig * 2;
                bh[nt][0] = *(const uint32_t*)(sBh + e0);
                bh[nt][1] = *(const uint32_t*)(sBh + e0 + 8);
                bl[nt][0] = *(const uint32_t*)(sBl + e0);
                bl[nt][1] = *(const uint32_t*)(sBl + e0 + 8);
            }
            #pragma unroll
            for (int mt = 0; mt < 4; mt++)
                #pragma unroll
                for (int nt = 0; nt < 4; nt++) {
                    mma16816(c[mt][nt], ah[mt], bh[nt]);
                    mma16816(c[mt][nt], ah[mt], bl[nt]);
                    mma16816(c[mt][nt], al[mt], bh[nt]);
                }
        }
        __syncthreads();
    }

    // ---- epilogue: tanh + dot, reduce to per-row sums ----
    #pragma unroll
    for (int mt = 0; mt < 4; mt++) {
        #pragma unroll
        for (int h = 0; h < 2; h++) {
            int rowLocal = wm * 64 + mt * 16 + gro + h * 8;
            int m = m0 + rowLocal;
            int b = m & 63;
            const float* bias;
            const float* vv;
            if (gid == 0)      { bias = g_hw + b * 512;          vv = vz; }
            else if (gid == 1) { bias = g_hw + 32768 + b * 512;  vv = vu; }
            else               { bias = bc2;                     vv = g_h1 + b * 512; }
            float s = 0.f;
            #pragma unroll
            for (int nt = 0; nt < 4; nt++) {
                #pragma unroll
                for (int j = 0; j < 2; j++) {
                    int n = n0 + wn * 32 + nt * 8 + tig * 2 + j;
                    float x = c[mt][nt][h * 2 + j] + bias[n];
                    float th = (gid == 2) ? tanhf(x) : tanh_fast(x);
                    s += th * vv[n];
                }
            }
            s += __shfl_xor_sync(0xffffffffu, s, 1);
            s += __shfl_xor_sync(0xffffffffu, s, 2);
            if (tig == 0) rs[rowLocal * 5 + wn] = s;
        }
    }
    __syncthreads();
    if (tid < 128) {
        float s = rs[tid * 5 + 0] + rs[tid * 5 + 1] + rs[tid * 5 + 2] + rs[tid * 5 + 3];
        int m = m0 + tid;
        int b = m & 63, t = m >> 6;
        int oidx = (gid == 2) ? 4 : gid;
        atomicAdd(&g_accbuf[oidx * 32768 + b * 512 + t], s);
    }
}

// softmax over t per (which,b); rows 0..63 = e_z, 64..127 = e_u (contiguous)
__global__ void k_softmax_rows() {
    __shared__ float sh[16];
    float* row = g_accbuf + (size_t)blockIdx.x * 512;
    float x = row[threadIdx.x];
    float m = blockReduceMax(x, sh);
    float e = expf(x - m);
    float s = blockReduceSum(e, sh);
    row[threadIdx.x] = e / s;
}

// ctx[b,h] += sum_{t in slice} a[b,t] * enc[t,b,h]
__global__ void k_ctx(const float* __restrict__ z_enc, const float* __restrict__ u_enc) {
    int which = blockIdx.z;
    int b  = blockIdx.y;
    int t0 = blockIdx.x * 64;
    int h  = threadIdx.x;
    const float* enc = which ? u_enc : z_enc;
    const float* a   = g_accbuf + which * 32768 + b * 512;
    float* ctx = g_accbuf + (2 + which) * 32768 + b * 512;
    __shared__ float sa[64];
    if (h < 64) sa[h] = a[t0 + h];
    __syncthreads();
    float s = 0.f;
    #pragma unroll 8
    for (int tt = 0; tt < 64; tt++)
        s += sa[tt] * enc[((size_t)(t0 + tt) * 64 + b) * 512 + h];
    atomicAdd(&ctx[h], s);
}

// x = [m_embed(256), u_ctx(512), z_ctx(512), degree(5)]
__global__ void k_assemble(const float* __restrict__ emb, const int* __restrict__ mt,
                           const float* __restrict__ degree) {
    int b = blockIdx.x, tid = threadIdx.x;
    float* xr = g_x + b * XPADc;
    const float* ctxz = g_accbuf + 2 * 32768 + b * 512;
    const float* ctxu = g_accbuf + 3 * 32768 + b * 512;
    int m = mt[b];
    if (tid < 256) xr[tid] = emb[(size_t)m * Ec + tid];
    xr[256 + tid] = ctxu[tid];
    xr[768 + tid] = ctxz[tid];
    if (tid < 5) xr[1280 + tid] = degree[b * Dc + tid];
}

// gi[b,g] = b_ih[g] + x[b,:]·W_ih[g,:] ; gh[b,g] = b_hh[g] + h0[b,:]·W_hh[g,:]
__global__ void __launch_bounds__(256)
k_gates(const float* __restrict__ W_ih, const float* __restrict__ W_hh,
        const float* __restrict__ b_ih, const float* __restrict__ b_hh,
        const float* __restrict__ h0) {
    int b = threadIdx.x & 63;
    int g = blockIdx.x * 4 + (threadIdx.x >> 6);
    const float* xr = g_x + b * XPADc;
    const float* wr = W_ih + (size_t)g * GINc;
    float acc = b_ih[g];
    #pragma unroll 5
    for (int j = 0; j < GINc; j++) acc += xr[j] * wr[j];
    g_gi[b * G3c + g] = acc;
    const float* hr = h0 + b * 512;
    const float* wh = W_hh + (size_t)g * 512;
    float a2 = b_hh[g];
    #pragma unroll 8
    for (int j = 0; j < 512; j++) a2 += hr[j] * wh[j];
    g_gh[b * G3c + g] = a2;
}

__global__ void k_h1(const float* __restrict__ h0, float* __restrict__ out) {
    int b = blockIdx.x, h = threadIdx.x;
    float ir = g_gi[b * G3c + h],        hr = g_gh[b * G3c + h];
    float iz = g_gi[b * G3c + 512 + h],  hz = g_gh[b * G3c + 512 + h];
    float in_ = g_gi[b * G3c + 1024 + h], hn = g_gh[b * G3c + 1024 + h];
    float r = 1.f / (1.f + expf(-(ir + hr)));
    float z = 1.f / (1.f + expf(-(iz + hz)));
    float n = tanhf(in_ + r * hn);
    float hv = (1.f - z) * n + z * h0[b * 512 + h];
    g_h1[b * 512 + h] = hv;
    out[Bc * VTc + b * 512 + h] = hv;                 // h1 copy 1
    out[Bc * VTc + Bc * 512 + b * 512 + h] = hv;      // h1 copy 2
}

// gen_score[b,v] = [z_ctx,u_ctx,h1]·W_proj[:,v] + b_proj[v] -> logits[:, :3000]
__global__ void __launch_bounds__(128)
k_proj(const float* __restrict__ W_proj, const float* __restrict__ b_proj) {
    __shared__ float sx[8][G3c];
    int b0 = blockIdx.y * 8;
    int tid = threadIdx.x;
    for (int i = tid; i < 8 * G3c; i += 128) {
        int bl = i / G3c, j = i % G3c;
        int b = b0 + bl;
        float v;
        if (j < 512)       v = g_accbuf[2 * 32768 + b * 512 + j];          // z_ctx
        else if (j < 1024) v = g_accbuf[3 * 32768 + b * 512 + (j - 512)];  // u_ctx
        else               v = g_h1[b * 512 + (j - 1024)];
        sx[bl][j] = v;
    }
    __syncthreads();
    int v = blockIdx.x * 128 + tid;
    if (v >= Vc) return;
    float acc[8];
    float bp = b_proj[v];
    #pragma unroll
    for (int bl = 0; bl < 8; bl++) acc[bl] = bp;
    for (int j = 0; j < G3c; j++) {
        float w = W_proj[(size_t)j * Vc + v];
        #pragma unroll
        for (int bl = 0; bl < 8; bl++) acc[bl] += sx[bl][j] * w;
    }
    #pragma unroll
    for (int bl = 0; bl < 8; bl++)
        g_logits[(size_t)(b0 + bl) * LTc + v] = acc[bl];
}

// m[b] = max_t cs ; ecs = exp(cs - m)
__global__ void k_rowmax() {
    __shared__ float sh[16];
    int b = blockIdx.x, t = threadIdx.x;
    float c = g_accbuf[4 * 32768 + b * 512 + t];
    float m = blockReduceMax(c, sh);
    g_ecs[b * 512 + t] = expf(c - m);
    if (t == 0) g_mrow[b] = m;
}

// z_copy[b,v] = log(sum_t ecs[b,t]*sparse[b,t,v]) + m[b] -> logits[:, 3000:]
__global__ void __launch_bounds__(128)
k_zcopy(const float* __restrict__ sparse) {
    __shared__ float se[512];
    int b = blockIdx.y;
    int tid = threadIdx.x;
    for (int i = tid; i < 512; i += 128) se[i] = g_ecs[b * 512 + i];
    __syncthreads();
    int v = blockIdx.x * 128 + tid;
    if (v >= VTc) return;
    const float* sp = sparse + (size_t)b * TZc * VTc + v;
    float s = 0.f;
    #pragma unroll 4
    for (int t = 0; t < 512; t++) s += se[t] * sp[(size_t)t * VTc];
    g_logits[(size_t)b * LTc + Vc + v] = logf(s) + g_mrow[b];
}

// final softmax over 6512 + recombine: proba[v<3000]=gen+cpy[v]; tail = cpy[3000:]
__global__ void k_final(float* __restrict__ out) {
    __shared__ float sh[16];
    int b = blockIdx.x, tid = threadIdx.x;
    const float* l = g_logits + (size_t)b * LTc;
    float m = -1e30f;
    for (int i = tid; i < LTc; i += 512) m = fmaxf(m, l[i]);
    m = blockReduceMax(m, sh);
    float s = 0.f;
    for (int i = tid; i < LTc; i += 512) s += expf(l[i] - m);
    s = blockReduceSum(s, sh);
    float inv = 1.f / s;
    float* op = out + (size_t)b * VTc;
    for (int v = tid; v < Vc; v += 512)
        op[v] = (expf(l[v] - m) + expf(l[Vc + v] - m)) * inv;
    for (int k2 = tid; k2 < 512; k2 += 512)
        op[Vc + k2] = expf(l[2 * Vc + k2] - m) * inv;
}

// ---------------- launch ------------------------------------------------------
extern "C" void kernel_launch(void* const* d_in, const int* in_sizes, int n_in,
                              void* d_out, int out_size) {
    (void)in_sizes; (void)n_in; (void)out_size;
    const float* z_enc  = (const float*)d_in[0];
    const float* u_enc  = (const float*)d_in[1];
    const int*   mt     = (const int*)  d_in[2];
    const float* degree = (const float*)d_in[3];
    const float* h0     = (const float*)d_in[4];
    const float* sparse = (const float*)d_in[5];
    const float* emb    = (const float*)d_in[6];
    const float* Wz     = (const float*)d_in[7];
    const float* bz     = (const float*)d_in[8];
    const float* vz     = (const float*)d_in[9];
    const float* Wu     = (const float*)d_in[10];
    const float* bu     = (const float*)d_in[11];
    const float* vu     = (const float*)d_in[12];
    const float* W_ih   = (const float*)d_in[13];
    const float* W_hh   = (const float*)d_in[14];
    const float* b_ih   = (const float*)d_in[15];
    const float* b_hh   = (const float*)d_in[16];
    const float* W_proj = (const float*)d_in[17];
    const float* b_proj = (const float*)d_in[18];
    const float* Wc2    = (const float*)d_in[19];
    const float* bc2    = (const float*)d_in[20];
    float* out = (float*)d_out;

    cudaFuncSetAttribute(k_mma_gemm, cudaFuncAttributeMaxDynamicSharedMemorySize, GEMM_SMEM);

    k_zero<<<320, 512>>>();
    k_prep_w<<<dim3(16, 16, 3), dim3(32, 8)>>>(Wz, Wu, Wc2);
    k_hW<<<dim3(Bc, 2), 512>>>(h0, Wz, bz, Wu, bu);

    // attention energy GEMMs (ids 0,1) on tensor cores (mma.sync)
    k_mma_gemm<<<dim3(256, 4, 2), 256, GEMM_SMEM>>>(z_enc, u_enc, vz, vu, bc2, 0);

    k_softmax_rows<<<128, 512>>>();
    k_ctx<<<dim3(8, Bc, 2), 512>>>(z_enc, u_enc);

    k_assemble<<<Bc, 512>>>(emb, mt, degree);
    k_gates<<<G3c / 4, 256>>>(W_ih, W_hh, b_ih, b_hh, h0);
    k_h1<<<Bc, 512>>>(h0, out);

    k_proj<<<dim3(24, 8), 128>>>(W_proj, b_proj);

    // cs GEMM (id 2) — depends on h1
    k_mma_gemm<<<dim3(256, 4, 1), 256, GEMM_SMEM>>>(z_enc, u_enc, vz, vu, bc2, 2);

    k_rowmax<<<Bc, 512>>>();
    k_zcopy<<<dim3(28, Bc), 128>>>(sparse);
    k_final<<<Bc, 512>>>(out);
}

// round 4
// speedup vs baseline: 1.7468x; 1.0946x over previous
#include <cuda_runtime.h>
#include <cuda_bf16.h>
#include <math.h>
#include <cstdint>

// Problem constants
#define TZc 512
#define Bc  64
#define Hc  512
#define Ec  256
#define Vc  3000
#define Dc  5
#define VTc 3512          // V + TZ
#define GINc 1285         // E + 2H + D
#define XPADc 1288
#define G3c 1536          // 3H
#define LTc 6512          // V + VT

// ---------------- scratch (device globals; no allocation allowed) ------------
// g_accbuf layout: [0]=e_z, [1]=e_u, [2]=ctx_z, [3]=ctx_u, [4]=cs  (each 64x512)
__device__ float g_accbuf[5 * 32768];
__device__ float g_hw[2 * 32768];      // hWz, hWu  (h0 @ W[:H] + b)
__device__ float g_x[Bc * XPADc];      // GRU input (padded stride)
__device__ float g_gi[Bc * G3c];
__device__ float g_gh[Bc * G3c];
__device__ float g_h1[Bc * Hc];
__device__ float g_ecs[Bc * TZc];
__device__ float g_mrow[Bc];
__device__ float g_logits[Bc * LTc];
// transposed split-bf16 weights: [gemm][n][k], gemm: 0=Wz2, 1=Wu2, 2=Wc2
__device__ __nv_bfloat16 g_wt_hi[3 * 512 * 512];
__device__ __nv_bfloat16 g_wt_lo[3 * 512 * 512];

// ---------------- helpers ------------------------------------------------------
__device__ __forceinline__ float tanh_fast(float x) {
    float y;
    asm("tanh.approx.f32 %0, %1;" : "=f"(y) : "f"(x));
    return y;
}
__device__ __forceinline__ void mma16816(float* c, const uint32_t* a, const uint32_t* b) {
    asm volatile(
        "mma.sync.aligned.m16n8k16.row.col.f32.bf16.bf16.f32 "
        "{%0,%1,%2,%3}, {%4,%5,%6,%7}, {%8,%9}, {%0,%1,%2,%3};"
        : "+f"(c[0]), "+f"(c[1]), "+f"(c[2]), "+f"(c[3])
        : "r"(a[0]), "r"(a[1]), "r"(a[2]), "r"(a[3]), "r"(b[0]), "r"(b[1]));
}
__device__ __forceinline__ uint32_t smem_u32(const void* p) {
    uint32_t a;
    asm("{ .reg .u64 t; cvta.to.shared.u64 t, %1; cvt.u32.u64 %0, t; }" : "=r"(a) : "l"(p));
    return a;
}
__device__ __forceinline__ void ldsm_x4(uint32_t& r0, uint32_t& r1, uint32_t& r2,
                                        uint32_t& r3, uint32_t addr) {
    asm volatile("ldmatrix.sync.aligned.m8n8.x4.shared.b16 {%0,%1,%2,%3}, [%4];"
                 : "=r"(r0), "=r"(r1), "=r"(r2), "=r"(r3) : "r"(addr));
}
__device__ __forceinline__ void cpasync16(uint32_t dst, const void* src) {
    asm volatile("cp.async.cg.shared.global [%0], [%1], 16;" :: "r"(dst), "l"(src));
}

// ---------------- block reductions -------------------------------------------
__device__ __forceinline__ float blockReduceMax(float v, float* sh) {
    #pragma unroll
    for (int o = 16; o; o >>= 1) v = fmaxf(v, __shfl_xor_sync(0xffffffffu, v, o));
    if ((threadIdx.x & 31) == 0) sh[threadIdx.x >> 5] = v;
    __syncthreads();
    float r = sh[0];
    int nw = (blockDim.x + 31) >> 5;
    for (int j = 1; j < nw; j++) r = fmaxf(r, sh[j]);
    __syncthreads();
    return r;
}
__device__ __forceinline__ float blockReduceSum(float v, float* sh) {
    #pragma unroll
    for (int o = 16; o; o >>= 1) v += __shfl_xor_sync(0xffffffffu, v, o);
    if ((threadIdx.x & 31) == 0) sh[threadIdx.x >> 5] = v;
    __syncthreads();
    float r = 0.f;
    int nw = (blockDim.x + 31) >> 5;
    for (int j = 0; j < nw; j++) r += sh[j];
    __syncthreads();
    return r;
}

// ---------------- kernels -----------------------------------------------------

__global__ void k_zero() {
    int i = blockIdx.x * blockDim.x + threadIdx.x;
    if (i < 5 * 32768) g_accbuf[i] = 0.f;
}

// Transpose + split fp32 weights -> bf16 hi/lo [n][k].
// which 0: Wz[H:2H], 1: Wu[H:2H], 2: Wc2
__global__ void k_prep_w(const float* __restrict__ Wz, const float* __restrict__ Wu,
                         const float* __restrict__ Wc2) {
    __shared__ float ts[32][33];
    int which = blockIdx.z;
    const float* W = (which == 0) ? (Wz + 512 * 512) : (which == 1) ? (Wu + 512 * 512) : Wc2;
    int k0 = blockIdx.y * 32, n0 = blockIdx.x * 32;
    int tx = threadIdx.x, ty = threadIdx.y;   // 32 x 8
    #pragma unroll
    for (int j = 0; j < 32; j += 8)
        ts[ty + j][tx] = W[(size_t)(k0 + ty + j) * 512 + n0 + tx];
    __syncthreads();
    __nv_bfloat16* oh = g_wt_hi + (size_t)which * 262144;
    __nv_bfloat16* ol = g_wt_lo + (size_t)which * 262144;
    #pragma unroll
    for (int j = 0; j < 32; j += 8) {
        float x = ts[tx][ty + j];
        __nv_bfloat16 h = __float2bfloat16(x);
        __nv_bfloat16 l = __float2bfloat16(x - __bfloat162float(h));
        size_t idx = (size_t)(n0 + ty + j) * 512 + k0 + tx;
        oh[idx] = h; ol[idx] = l;
    }
}

// hW[b,k] = sum_j h0[b,j] * W[j,k] + bias[k]   (W = first H rows of Wz/Wu)
__global__ void k_hW(const float* __restrict__ h0,
                     const float* __restrict__ Wz, const float* __restrict__ bz,
                     const float* __restrict__ Wu, const float* __restrict__ bu) {
    int b = blockIdx.x, which = blockIdx.y, k = threadIdx.x;
    const float* W  = which ? Wu : Wz;
    const float* bb = which ? bu : bz;
    float* o = g_hw + which * 32768;
    __shared__ float sh[512];
    sh[k] = h0[b * 512 + k];
    __syncthreads();
    float acc = bb[k];
    #pragma unroll 8
    for (int j = 0; j < 512; j++) acc += sh[j] * W[j * 512 + k];
    o[b * 512 + k] = acc;
}

// ---------------- mma.sync fused GEMM + tanh-dot epilogue ---------------------
// gemm id (gemm_base + blockIdx.z): 0 = attn-z, 1 = attn-u, 2 = cs
// C = A(32768x512) @ W2(512x512); CTA tile 64(M) x 128(N), K chunk 64.
// 8 warps: wm = wid>>1 (16 rows each), wn = wid&1 (64 cols each).
// out[b*512+t] += sum_n tanh(C[m,n] + bias) * v,  m = t*64+b; t == blockIdx.x
#define SA_STRIDE 72                      // bf16 elems per smem row (64 + 8 pad)
#define SMA (64 * SA_STRIDE)              // A tile elems (per hi/lo)
#define SMB (128 * SA_STRIDE)             // B tile elems (per hi/lo)
#define GEMM_SMEM ((2 * SMA + 2 * SMB) * 2)   // 55296 B
__global__ void __launch_bounds__(256, 2)
k_mma_gemm(const float* __restrict__ z_enc, const float* __restrict__ u_enc,
           const float* __restrict__ vz, const float* __restrict__ vu,
           const float* __restrict__ bc2, int gemm_base) {
    extern __shared__ char smem_raw[];
    __nv_bfloat16* sAh = (__nv_bfloat16*)smem_raw;
    __nv_bfloat16* sAl = sAh + SMA;
    __nv_bfloat16* sBh = sAl + SMA;
    __nv_bfloat16* sBl = sBh + SMB;
    const uint32_t uAh = smem_u32(sAh);
    const uint32_t uAl = smem_u32(sAl);
    const uint32_t uBh = smem_u32(sBh);
    const uint32_t uBl = smem_u32(sBl);

    const int tid = threadIdx.x;
    const int wid = tid >> 5;
    const int lane = tid & 31;
    const int gro = lane >> 2;     // groupID
    const int tig = lane & 3;      // thread-in-group
    const int wm = wid >> 1;       // 0..3  (M, 16 rows)
    const int wn = wid & 1;        // 0..1  (N, 64 cols)

    const int gid = gemm_base + blockIdx.z;
    const int m0 = blockIdx.x * 64;
    const int n0 = blockIdx.y * 128;

    const float* A = (gid == 1) ? u_enc : z_enc;
    const __nv_bfloat16* WtH = g_wt_hi + (size_t)gid * 262144;
    const __nv_bfloat16* WtL = g_wt_lo + (size_t)gid * 262144;

    // ldmatrix source addresses (element offsets within tiles)
    // A (m16k16): lanes 0-7 rows r+0..7 @k0 | 8-15 rows+8 @k0 | 16-23 rows @k+8 | 24-31 rows+8 @k+8
    const int a_row = wm * 16 + (lane & 7) + ((lane & 8) ? 8 : 0);
    const int a_koff = (lane & 16) ? 8 : 0;
    // B (n16k16): lanes 0-7 n+0..7 @k0 | 8-15 n+0..7 @k+8 | 16-23 n+8..15 @k0 | 24-31 n+8..15 @k+8
    const int b_rowbase = wn * 64 + (lane & 7) + ((lane & 16) ? 8 : 0);
    const int b_koff = (lane & 8) ? 8 : 0;

    float c[8][4];
    #pragma unroll
    for (int i = 0; i < 8; i++)
        #pragma unroll
        for (int r = 0; r < 4; r++) c[i][r] = 0.f;

    for (int kk = 0; kk < 512; kk += 64) {
        // ---- B tiles via cp.async: 128 n-rows x 64 k bf16, hi+lo = 2048 16B lines
        #pragma unroll
        for (int i = 0; i < 8; i++) {
            int idx = tid + i * 256;           // 0..2047
            int buf = idx >> 10;               // 0 = hi, 1 = lo
            int line = idx & 1023;
            int row = line >> 3;
            int kq = line & 7;
            uint32_t dst = (buf ? uBl : uBh) + (uint32_t)(row * SA_STRIDE + kq * 8) * 2;
            const __nv_bfloat16* src = (buf ? WtL : WtH) + (size_t)(n0 + row) * 512 + kk + kq * 8;
            cpasync16(dst, src);
        }
        asm volatile("cp.async.commit_group;");
        // ---- A chunk (64 x 64 fp32), split into bf16 hi/lo ----
        #pragma unroll
        for (int i = 0; i < 4; i++) {
            int idx = tid + i * 256;           // 0..1023 float4 units
            int row = idx >> 4;
            int k4  = idx & 15;
            float4 v = ((const float4*)(A + (size_t)(m0 + row) * 512 + kk))[k4];
            float xs[4] = {v.x, v.y, v.z, v.w};
            union { uint2 u; __nv_bfloat16 h[4]; } ph, pl;
            #pragma unroll
            for (int j = 0; j < 4; j++) {
                __nv_bfloat16 hh = __float2bfloat16(xs[j]);
                ph.h[j] = hh;
                pl.h[j] = __float2bfloat16(xs[j] - __bfloat162float(hh));
            }
            int e = row * SA_STRIDE + k4 * 4;
            *(uint2*)(sAh + e) = ph.u;
            *(uint2*)(sAl + e) = pl.u;
        }
        asm volatile("cp.async.wait_group 0;");
        __syncthreads();

        #pragma unroll
        for (int ks = 0; ks < 4; ks++) {
            uint32_t ah[4], al[4];
            uint32_t aoff = (uint32_t)(a_row * SA_STRIDE + ks * 16 + a_koff) * 2;
            ldsm_x4(ah[0], ah[1], ah[2], ah[3], uAh + aoff);
            ldsm_x4(al[0], al[1], al[2], al[3], uAl + aoff);
            #pragma unroll
            for (int nt2 = 0; nt2 < 4; nt2++) {
                uint32_t boff = (uint32_t)((b_rowbase + nt2 * 16) * SA_STRIDE + ks * 16 + b_koff) * 2;
                uint32_t b0, b1, b2, b3;
                ldsm_x4(b0, b1, b2, b3, uBh + boff);
                uint32_t beh[2] = {b0, b1}, boh[2] = {b2, b3};
                mma16816(c[nt2 * 2],     ah, beh);
                mma16816(c[nt2 * 2 + 1], ah, boh);
                mma16816(c[nt2 * 2],     al, beh);
                mma16816(c[nt2 * 2 + 1], al, boh);
                ldsm_x4(b0, b1, b2, b3, uBl + boff);
                uint32_t bel[2] = {b0, b1}, bol[2] = {b2, b3};
                mma16816(c[nt2 * 2],     ah, bel);
                mma16816(c[nt2 * 2 + 1], ah, bol);
            }
        }
        __syncthreads();
    }

    // ---- epilogue: tanh + dot over this warp's 64 columns, exclusive rows ----
    const int t = blockIdx.x;
    #pragma unroll
    for (int h = 0; h < 2; h++) {
        int b = wm * 16 + gro + h * 8;     // rowLocal == b since m0 % 64 == 0
        const float* bias;
        const float* vv;
        if (gid == 0)      { bias = g_hw + b * 512;          vv = vz; }
        else if (gid == 1) { bias = g_hw + 32768 + b * 512;  vv = vu; }
        else               { bias = bc2;                     vv = g_h1 + b * 512; }
        float s = 0.f;
        #pragma unroll
        for (int nt = 0; nt < 8; nt++) {
            #pragma unroll
            for (int j = 0; j < 2; j++) {
                int n = n0 + wn * 64 + nt * 8 + tig * 2 + j;
                float x = c[nt][h * 2 + j] + bias[n];
                float th = (gid == 2) ? tanhf(x) : tanh_fast(x);
                s += th * vv[n];
            }
        }
        s += __shfl_xor_sync(0xffffffffu, s, 1);
        s += __shfl_xor_sync(0xffffffffu, s, 2);
        if (tig == 0) {
            int oidx = (gid == 2) ? 4 : gid;
            atomicAdd(&g_accbuf[oidx * 32768 + b * 512 + t], s);
        }
    }
}

// softmax over t per (which,b); rows 0..63 = e_z, 64..127 = e_u (contiguous)
__global__ void k_softmax_rows() {
    __shared__ float sh[16];
    float* row = g_accbuf + (size_t)blockIdx.x * 512;
    float x = row[threadIdx.x];
    float m = blockReduceMax(x, sh);
    float e = expf(x - m);
    float s = blockReduceSum(e, sh);
    row[threadIdx.x] = e / s;
}

// ctx[b,h] += sum_{t in slice} a[b,t] * enc[t,b,h]
__global__ void k_ctx(const float* __restrict__ z_enc, const float* __restrict__ u_enc) {
    int which = blockIdx.z;
    int b  = blockIdx.y;
    int t0 = blockIdx.x * 64;
    int h  = threadIdx.x;
    const float* enc = which ? u_enc : z_enc;
    const float* a   = g_accbuf + which * 32768 + b * 512;
    float* ctx = g_accbuf + (2 + which) * 32768 + b * 512;
    __shared__ float sa[64];
    if (h < 64) sa[h] = a[t0 + h];
    __syncthreads();
    float s = 0.f;
    #pragma unroll 8
    for (int tt = 0; tt < 64; tt++)
        s += sa[tt] * enc[((size_t)(t0 + tt) * 64 + b) * 512 + h];
    atomicAdd(&ctx[h], s);
}

// x = [m_embed(256), u_ctx(512), z_ctx(512), degree(5)]
__global__ void k_assemble(const float* __restrict__ emb, const int* __restrict__ mt,
                           const float* __restrict__ degree) {
    int b = blockIdx.x, tid = threadIdx.x;
    float* xr = g_x + b * XPADc;
    const float* ctxz = g_accbuf + 2 * 32768 + b * 512;
    const float* ctxu = g_accbuf + 3 * 32768 + b * 512;
    int m = mt[b];
    if (tid < 256) xr[tid] = emb[(size_t)m * Ec + tid];
    xr[256 + tid] = ctxu[tid];
    xr[768 + tid] = ctxz[tid];
    if (tid < 5) xr[1280 + tid] = degree[b * Dc + tid];
}

// gi[b,g] = b_ih[g] + x[b,:]·W_ih[g,:] ; gh[b,g] = b_hh[g] + h0[b,:]·W_hh[g,:]
__global__ void __launch_bounds__(256)
k_gates(const float* __restrict__ W_ih, const float* __restrict__ W_hh,
        const float* __restrict__ b_ih, const float* __restrict__ b_hh,
        const float* __restrict__ h0) {
    int b = threadIdx.x & 63;
    int g = blockIdx.x * 4 + (threadIdx.x >> 6);
    const float* xr = g_x + b * XPADc;
    const float* wr = W_ih + (size_t)g * GINc;
    float acc = b_ih[g];
    #pragma unroll 5
    for (int j = 0; j < GINc; j++) acc += xr[j] * wr[j];
    g_gi[b * G3c + g] = acc;
    const float* hr = h0 + b * 512;
    const float* wh = W_hh + (size_t)g * 512;
    float a2 = b_hh[g];
    #pragma unroll 8
    for (int j = 0; j < 512; j++) a2 += hr[j] * wh[j];
    g_gh[b * G3c + g] = a2;
}

__global__ void k_h1(const float* __restrict__ h0, float* __restrict__ out) {
    int b = blockIdx.x, h = threadIdx.x;
    float ir = g_gi[b * G3c + h],        hr = g_gh[b * G3c + h];
    float iz = g_gi[b * G3c + 512 + h],  hz = g_gh[b * G3c + 512 + h];
    float in_ = g_gi[b * G3c + 1024 + h], hn = g_gh[b * G3c + 1024 + h];
    float r = 1.f / (1.f + expf(-(ir + hr)));
    float z = 1.f / (1.f + expf(-(iz + hz)));
    float n = tanhf(in_ + r * hn);
    float hv = (1.f - z) * n + z * h0[b * 512 + h];
    g_h1[b * 512 + h] = hv;
    out[Bc * VTc + b * 512 + h] = hv;                 // h1 copy 1
    out[Bc * VTc + Bc * 512 + b * 512 + h] = hv;      // h1 copy 2
}

// gen_score[b,v] = [z_ctx,u_ctx,h1]·W_proj[:,v] + b_proj[v] -> logits[:, :3000]
__global__ void __launch_bounds__(128)
k_proj(const float* __restrict__ W_proj, const float* __restrict__ b_proj) {
    __shared__ float sx[8][G3c];
    int b0 = blockIdx.y * 8;
    int tid = threadIdx.x;
    for (int i = tid; i < 8 * G3c; i += 128) {
        int bl = i / G3c, j = i % G3c;
        int b = b0 + bl;
        float v;
        if (j < 512)       v = g_accbuf[2 * 32768 + b * 512 + j];          // z_ctx
        else if (j < 1024) v = g_accbuf[3 * 32768 + b * 512 + (j - 512)];  // u_ctx
        else               v = g_h1[b * 512 + (j - 1024)];
        sx[bl][j] = v;
    }
    __syncthreads();
    int v = blockIdx.x * 128 + tid;
    if (v >= Vc) return;
    float acc[8];
    float bp = b_proj[v];
    #pragma unroll
    for (int bl = 0; bl < 8; bl++) acc[bl] = bp;
    for (int j = 0; j < G3c; j++) {
        float w = W_proj[(size_t)j * Vc + v];
        #pragma unroll
        for (int bl = 0; bl < 8; bl++) acc[bl] += sx[bl][j] * w;
    }
    #pragma unroll
    for (int bl = 0; bl < 8; bl++)
        g_logits[(size_t)(b0 + bl) * LTc + v] = acc[bl];
}

// m[b] = max_t cs ; ecs = exp(cs - m)
__global__ void k_rowmax() {
    __shared__ float sh[16];
    int b = blockIdx.x, t = threadIdx.x;
    float c = g_accbuf[4 * 32768 + b * 512 + t];
    float m = blockReduceMax(c, sh);
    g_ecs[b * 512 + t] = expf(c - m);
    if (t == 0) g_mrow[b] = m;
}

// z_copy[b,v] = log(sum_t ecs[b,t]*sparse[b,t,v]) + m[b] -> logits[:, 3000:]
__global__ void __launch_bounds__(128)
k_zcopy(const float* __restrict__ sparse) {
    __shared__ float se[512];
    int b = blockIdx.y;
    int tid = threadIdx.x;
    for (int i = tid; i < 512; i += 128) se[i] = g_ecs[b * 512 + i];
    __syncthreads();
    int v = blockIdx.x * 128 + tid;
    if (v >= VTc) return;
    const float* sp = sparse + (size_t)b * TZc * VTc + v;
    float s = 0.f;
    #pragma unroll 8
    for (int t = 0; t < 512; t++) s += se[t] * sp[(size_t)t * VTc];
    g_logits[(size_t)b * LTc + Vc + v] = logf(s) + g_mrow[b];
}

// final softmax over 6512 + recombine: proba[v<3000]=gen+cpy[v]; tail = cpy[3000:]
__global__ void k_final(float* __restrict__ out) {
    __shared__ float sh[16];
    int b = blockIdx.x, tid = threadIdx.x;
    const float* l = g_logits + (size_t)b * LTc;
    float m = -1e30f;
    for (int i = tid; i < LTc; i += 512) m = fmaxf(m, l[i]);
    m = blockReduceMax(m, sh);
    float s = 0.f;
    for (int i = tid; i < LTc; i += 512) s += expf(l[i] - m);
    s = blockReduceSum(s, sh);
    float inv = 1.f / s;
    float* op = out + (size_t)b * VTc;
    for (int v = tid; v < Vc; v += 512)
        op[v] = (expf(l[v] - m) + expf(l[Vc + v] - m)) * inv;
    for (int k2 = tid; k2 < 512; k2 += 512)
        op[Vc + k2] = expf(l[2 * Vc + k2] - m) * inv;
}

// ---------------- launch ------------------------------------------------------
extern "C" void kernel_launch(void* const* d_in, const int* in_sizes, int n_in,
                              void* d_out, int out_size) {
    (void)in_sizes; (void)n_in; (void)out_size;
    const float* z_enc  = (const float*)d_in[0];
    const float* u_enc  = (const float*)d_in[1];
    const int*   mt     = (const int*)  d_in[2];
    const float* degree = (const float*)d_in[3];
    const float* h0     = (const float*)d_in[4];
    const float* sparse = (const float*)d_in[5];
    const float* emb    = (const float*)d_in[6];
    const float* Wz     = (const float*)d_in[7];
    const float* bz     = (const float*)d_in[8];
    const float* vz     = (const float*)d_in[9];
    const float* Wu     = (const float*)d_in[10];
    const float* bu     = (const float*)d_in[11];
    const float* vu     = (const float*)d_in[12];
    const float* W_ih   = (const float*)d_in[13];
    const float* W_hh   = (const float*)d_in[14];
    const float* b_ih   = (const float*)d_in[15];
    const float* b_hh   = (const float*)d_in[16];
    const float* W_proj = (const float*)d_in[17];
    const float* b_proj = (const float*)d_in[18];
    const float* Wc2    = (const float*)d_in[19];
    const float* bc2    = (const float*)d_in[20];
    float* out = (float*)d_out;

    cudaFuncSetAttribute(k_mma_gemm, cudaFuncAttributeMaxDynamicSharedMemorySize, GEMM_SMEM);

    k_zero<<<320, 512>>>();
    k_prep_w<<<dim3(16, 16, 3), dim3(32, 8)>>>(Wz, Wu, Wc2);
    k_hW<<<dim3(Bc, 2), 512>>>(h0, Wz, bz, Wu, bu);

    // attention energy GEMMs (ids 0,1) on tensor cores (mma.sync)
    k_mma_gemm<<<dim3(512, 4, 2), 256, GEMM_SMEM>>>(z_enc, u_enc, vz, vu, bc2, 0);

    k_softmax_rows<<<128, 512>>>();
    k_ctx<<<dim3(8, Bc, 2), 512>>>(z_enc, u_enc);

    k_assemble<<<Bc, 512>>>(emb, mt, degree);
    k_gates<<<G3c / 4, 256>>>(W_ih, W_hh, b_ih, b_hh, h0);
    k_h1<<<Bc, 512>>>(h0, out);

    k_proj<<<dim3(24, 8), 128>>>(W_proj, b_proj);

    // cs GEMM (id 2) — depends on h1
    k_mma_gemm<<<dim3(512, 4, 1), 256, GEMM_SMEM>>>(z_enc, u_enc, vz, vu, bc2, 2);

    k_rowmax<<<Bc, 512>>>();
    k_zcopy<<<dim3(28, Bc), 128>>>(sparse);
    k_final<<<Bc, 512>>>(out);
}